// round 17
// baseline (speedup 1.0000x reference)
#include <cuda_runtime.h>
#include <math.h>
#include <stdint.h>

#define TT 4096
#define BB 32
#define KK 16
#define LMM 256
#define LD 32
#define HH 256
#define AA 16
#define NRW 512
#define NTB 131072
#define XW 192
#define G3 768

typedef unsigned long long u64;

__device__ float g_xcat[(size_t)NTB * XW];
__device__ float g_gi[(size_t)NTB * G3];
__device__ float g_hid[(size_t)NTB * HH];
__device__ float g_logits[NTB * AA];
__device__ float g_dflag[NTB];
__device__ float g_mask[NTB];
__device__ int   g_dst[NTB];
__device__ int   g_cnt[NRW];
__device__ float g_Wc[XW * G3];
__device__ float g_bc[G3];
__device__ float4 g_Wh4[64 * G3];   /* [i/4][col] packed 4 consecutive rows */
__device__ float g_klp[512];

__device__ __forceinline__ u64 ffma2(u64 a, u64 b, u64 c) {
    u64 d; asm("fma.rn.f32x2 %0, %1, %2, %3;" : "=l"(d) : "l"(a), "l"(b), "l"(c)); return d;
}
__device__ __forceinline__ u64 splat2(float x) {
    u64 d; asm("mov.b64 %0, {%1, %1};" : "=l"(d) : "f"(x)); return d;
}
__device__ __forceinline__ float2 unpack2(u64 v) {
    float2 r; asm("mov.b64 {%0, %1}, %2;" : "=f"(r.x), "=f"(r.y) : "l"(v)); return r;
}

/* ================= launch 0: fused init + episode layout + weight prep ================= */
__global__ void initprep_k(const float* __restrict__ dones,
                           const float* __restrict__ Wsa, const float* __restrict__ bsa,
                           const float* __restrict__ Wi, const float* __restrict__ bi,
                           const float* __restrict__ Whh) {
    int bid = blockIdx.x, tid = threadIdx.x;
    if (bid == 0) {
        __shared__ float dch[256 * BB];
        for (int e = tid; e < NTB; e += 256) { g_dflag[e] = 0.f; g_mask[e] = 0.f; }
        for (int e = tid; e < NRW; e += 256) g_cnt[e] = 0;
        __syncthreads();
        int b = tid;
        int ep = 0, start = 0; float prev = 0.f;
        for (int tc = 0; tc < TT; tc += 256) {
            for (int e = tid; e < 256 * BB; e += 256) dch[e] = dones[tc * BB + e];
            __syncthreads();
            if (b < BB) for (int u = 0; u < 256; ++u) {
                int t = tc + u;
                if (t > 0 && prev > 0.5f) { ep++; start = t; }
                int pos = t - start;
                float d = dch[u * BB + b]; prev = d;
                int di = -1;
                if (ep < KK && pos < LMM) {
                    int row = b * KK + ep, slot = row * LMM + pos;
                    di = slot; g_dflag[slot] = d; g_mask[slot] = 1.f; g_cnt[row]++;
                }
                g_dst[t * BB + b] = di;
            }
            __syncthreads();
        }
    } else if (bid <= 579) {
        int idx = (bid - 1) * 256 + tid;          /* [0, 193*768) exactly */
        int a = idx / G3, j = idx % G3;
        const float* ar = (a < XW) ? (Wsa + a * HH) : bsa;
        float s = 0.f;
        for (int i = 0; i < HH; i++) s += ar[i] * Wi[i * G3 + j];
        if (a < XW) g_Wc[a * G3 + j] = s; else g_bc[j] = s + bi[j];
    } else {
        int w = (bid - 580) * 256 + tid;          /* [0, 64*768) exactly */
        int i4 = w / G3, col = w % G3;
        g_Wh4[w] = make_float4(Whh[(4 * i4 + 0) * G3 + col], Whh[(4 * i4 + 1) * G3 + col],
                               Whh[(4 * i4 + 2) * G3 + col], Whh[(4 * i4 + 3) * G3 + col]);
    }
}

/* ================= launch 1: fused se|ce embeddings + hid projection ================= */
__global__ void embed_k(const float* __restrict__ ST, const float* __restrict__ AC,
                        const float* __restrict__ MS,
                        const float* __restrict__ Wse, const float* __restrict__ bse,
                        const float* __restrict__ Wce, const float* __restrict__ bce,
                        const float* __restrict__ Whd, const float* __restrict__ bhd) {
    __shared__ __align__(16) float xs[160 * 16];   /* state | achar */
    __shared__ __align__(16) float hxs[96 * 16];   /* ce | ms       */
    int n0 = blockIdx.x * 16, tid = threadIdx.x;
    for (int e = tid; e < 16 * 160; e += 256) {
        int r = e / 160, i = e % 160;
        xs[i * 16 + r] = (i < 128) ? ST[(size_t)(n0 + r) * 128 + i]
                                   : AC[(size_t)(n0 + r) * 32 + (i - 128)];
    }
    for (int e = tid; e < 16 * 32; e += 256) {
        int r = e / 32, i = e % 32;
        hxs[(64 + i) * 16 + r] = MS[(size_t)(n0 + r) * 32 + i];
    }
    __syncthreads();
    const ulonglong2* X64 = (const ulonglong2*)xs;
    if (tid < 192) {
        u64 acc[8];
        int se = (tid < 128);
        int j = se ? tid : (tid - 128);
        int IN = se ? 128 : 32, OUT = se ? 128 : 64, ioff = se ? 0 : 128;
        const float* W = se ? Wse : Wce;
        u64 bs = splat2(se ? bse[j] : bce[j]);
#pragma unroll
        for (int k = 0; k < 8; k++) acc[k] = bs;
        for (int i = 0; i < IN; i++) {
            int ii = ioff + i;
            ulonglong2 x0 = X64[ii * 4 + 0], x1 = X64[ii * 4 + 1];
            ulonglong2 x2 = X64[ii * 4 + 2], x3 = X64[ii * 4 + 3];
            u64 ws = splat2(W[i * OUT + j]);
            acc[0] = ffma2(x0.x, ws, acc[0]); acc[1] = ffma2(x0.y, ws, acc[1]);
            acc[2] = ffma2(x1.x, ws, acc[2]); acc[3] = ffma2(x1.y, ws, acc[3]);
            acc[4] = ffma2(x2.x, ws, acc[4]); acc[5] = ffma2(x2.y, ws, acc[5]);
            acc[6] = ffma2(x3.x, ws, acc[6]); acc[7] = ffma2(x3.y, ws, acc[7]);
        }
        int jo = se ? j : (128 + j);
#pragma unroll
        for (int k = 0; k < 8; k++) {
            float2 v = unpack2(acc[k]);
            float va = fmaxf(v.x, 0.f), vb = fmaxf(v.y, 0.f);
            g_xcat[(size_t)(n0 + 2 * k) * XW + jo] = va;
            g_xcat[(size_t)(n0 + 2 * k + 1) * XW + jo] = vb;
            if (!se) { hxs[j * 16 + 2 * k] = va; hxs[j * 16 + 2 * k + 1] = vb; }
        }
    }
    __syncthreads();
    /* hid phase: all 256 threads, one output col each */
    const ulonglong2* H64 = (const ulonglong2*)hxs;
    int j = tid;
    u64 acc[8];
    u64 bs = splat2(bhd[j]);
#pragma unroll
    for (int k = 0; k < 8; k++) acc[k] = bs;
    for (int i = 0; i < 96; i++) {
        ulonglong2 x0 = H64[i * 4 + 0], x1 = H64[i * 4 + 1];
        ulonglong2 x2 = H64[i * 4 + 2], x3 = H64[i * 4 + 3];
        u64 ws = splat2(Whd[i * HH + j]);
        acc[0] = ffma2(x0.x, ws, acc[0]); acc[1] = ffma2(x0.y, ws, acc[1]);
        acc[2] = ffma2(x1.x, ws, acc[2]); acc[3] = ffma2(x1.y, ws, acc[3]);
        acc[4] = ffma2(x2.x, ws, acc[4]); acc[5] = ffma2(x2.y, ws, acc[5]);
        acc[6] = ffma2(x3.x, ws, acc[6]); acc[7] = ffma2(x3.y, ws, acc[7]);
    }
#pragma unroll
    for (int k = 0; k < 8; k++) {
        float2 v = unpack2(acc[k]);
        int da = g_dst[n0 + 2 * k];     if (da >= 0) g_hid[(size_t)da * HH + j] = v.x;
        int db = g_dst[n0 + 2 * k + 1]; if (db >= 0) g_hid[(size_t)db * HH + j] = v.y;
    }
}

/* ================= launch 2: gi GEMM (unchanged from passing R15) ================= */
#define AST 68
__global__ void __launch_bounds__(256, 1) gemm_k() {
    extern __shared__ float gs[];
    float* As = gs;
    float* Bs = gs + 192 * AST;
    int n0 = blockIdx.x * 64, j0 = blockIdx.y * 128, tid = threadIdx.x;
    int cg = tid & 15, rg = tid >> 4;
    const float4* Xc4 = (const float4*)g_xcat;
    const float4* Wc4 = (const float4*)g_Wc;
    for (int e = tid; e < 64 * 48; e += 256) {
        int r = e / 48, kq = e % 48;
        float4 x = Xc4[(size_t)(n0 + r) * 48 + kq];
        As[(4 * kq + 0) * AST + r] = x.x; As[(4 * kq + 1) * AST + r] = x.y;
        As[(4 * kq + 2) * AST + r] = x.z; As[(4 * kq + 3) * AST + r] = x.w;
    }
    float4* Bs4 = (float4*)Bs;
    for (int e = tid; e < 192 * 32; e += 256) {
        int k = e / 32, c4 = e % 32;
        Bs4[k * 32 + c4] = Wc4[(size_t)k * 192 + j0 / 4 + c4];
    }
    __syncthreads();
    u64 acc[4][4];
#pragma unroll
    for (int r = 0; r < 4; r++)
#pragma unroll
        for (int c = 0; c < 4; c++) acc[r][c] = 0ull;
    const ulonglong2* B64 = (const ulonglong2*)Bs;
#pragma unroll 4
    for (int k = 0; k < 192; k++) {
        float4 a = *(const float4*)(As + k * AST + rg * 4);
        ulonglong2 b_lo = B64[k * 32 + cg];
        ulonglong2 b_hi = B64[k * 32 + 16 + cg];
        float av[4] = {a.x, a.y, a.z, a.w};
#pragma unroll
        for (int r = 0; r < 4; r++) {
            u64 s = splat2(av[r]);
            acc[r][0] = ffma2(s, b_lo.x, acc[r][0]);
            acc[r][1] = ffma2(s, b_lo.y, acc[r][1]);
            acc[r][2] = ffma2(s, b_hi.x, acc[r][2]);
            acc[r][3] = ffma2(s, b_hi.y, acc[r][3]);
        }
    }
    float4 blo = *(const float4*)(g_bc + j0 + cg * 4);
    float4 bhi = *(const float4*)(g_bc + j0 + 64 + cg * 4);
#pragma unroll
    for (int r = 0; r < 4; r++) {
        int dn = g_dst[n0 + rg * 4 + r];
        if (dn >= 0) {
            float2 v0 = unpack2(acc[r][0]), v1 = unpack2(acc[r][1]);
            float2 v2 = unpack2(acc[r][2]), v3 = unpack2(acc[r][3]);
            float* op = g_gi + (size_t)dn * G3 + j0;
            *(float4*)(op + cg * 4) =
                make_float4(v0.x + blo.x, v0.y + blo.y, v1.x + blo.z, v1.y + blo.w);
            *(float4*)(op + 64 + cg * 4) =
                make_float4(v2.x + bhi.x, v2.y + bhi.y, v3.x + bhi.z, v3.y + bhi.w);
        }
    }
}

/* ================= launch 3 (PROFILED): GRU recurrence, 2-barrier pipelined ================= */
__global__ void __launch_bounds__(256, 1)
recur_k(const float* __restrict__ bh_, const float* __restrict__ Wout,
        const float* __restrict__ bout) {
    extern __shared__ float sm[];
    float4* whs4 = (float4*)sm;              /* 16*768 float4 = 196608B */
    float* hs_w = sm + 16 * G3 * 4;          /* post-reset h, [4][256]  */
    float* hs_l = hs_w + 1024;               /* pre-reset h (ys), [4][256] */
    float* wos = hs_l + 1024;                /* 256*17 */
    float* bos = wos + 256 * 17;             /* 16 */
    int t = threadIdx.x, row0 = blockIdx.x * 4;
    for (int e = t; e < 16 * G3; e += 256) whs4[e] = g_Wh4[e];
    for (int e = t; e < 256 * 16; e += 256) { int j = e >> 4, a = e & 15; wos[j * 17 + a] = Wout[e]; }
    if (t < 16) bos[t] = bout[t];
    float bh0 = bh_[t], bh1 = bh_[t + 256], bh2 = bh_[t + 512];
    float h[4];
#pragma unroll
    for (int r = 0; r < 4; r++) {
        h[r] = g_hid[(size_t)((row0 + r) * LMM) * HH + t];
        hs_w[r * 256 + t] = h[r];
    }
    int lr = t >> 6, sub = t & 63, la = sub >> 2, lq = sub & 3;
    const ulonglong2* ws64 = (const ulonglong2*)whs4;
    const ulonglong2* wg64 = (const ulonglong2*)g_Wh4;
    const ulonglong2* hpw = (const ulonglong2*)hs_w;   /* row r at hpw[r*64+i4] */
    __syncthreads();

    for (int p = 0; p < LMM; p++) {
        int s0 = (row0 + 0) * LMM + p;
        /* ---- phase X: prefetch gi(p), dflag(p+1); weight-loop(p); logits(p-1) ---- */
        float gi[4][3], dfn[4];
#pragma unroll
        for (int r = 0; r < 4; r++) {
            const float* gp = g_gi + (size_t)(s0 + r * LMM) * G3 + t;
            gi[r][0] = gp[0]; gi[r][1] = gp[256]; gi[r][2] = gp[512];
            dfn[r] = (p + 1 < LMM) ? g_dflag[s0 + r * LMM + 1] : 0.f;
        }
        u64 aR[4] = {0, 0, 0, 0}, aZ[4] = {0, 0, 0, 0}, aN[4] = {0, 0, 0, 0};
#pragma unroll 4
        for (int i4 = 0; i4 < 16; i4++) {
            ulonglong2 w0 = ws64[i4 * G3 + t];
            ulonglong2 w1 = ws64[i4 * G3 + t + 256];
            ulonglong2 w2 = ws64[i4 * G3 + t + 512];
#pragma unroll
            for (int r = 0; r < 4; r++) {
                ulonglong2 hv = hpw[r * 64 + i4];
                aR[r] = ffma2(hv.x, w0.x, aR[r]); aR[r] = ffma2(hv.y, w0.y, aR[r]);
                aZ[r] = ffma2(hv.x, w1.x, aZ[r]); aZ[r] = ffma2(hv.y, w1.y, aZ[r]);
                aN[r] = ffma2(hv.x, w2.x, aN[r]); aN[r] = ffma2(hv.y, w2.y, aN[r]);
            }
        }
#pragma unroll 4
        for (int i4 = 16; i4 < 64; i4++) {
            ulonglong2 w0 = wg64[i4 * G3 + t];
            ulonglong2 w1 = wg64[i4 * G3 + t + 256];
            ulonglong2 w2 = wg64[i4 * G3 + t + 512];
#pragma unroll
            for (int r = 0; r < 4; r++) {
                ulonglong2 hv = hpw[r * 64 + i4];
                aR[r] = ffma2(hv.x, w0.x, aR[r]); aR[r] = ffma2(hv.y, w0.y, aR[r]);
                aZ[r] = ffma2(hv.x, w1.x, aZ[r]); aZ[r] = ffma2(hv.y, w1.y, aZ[r]);
                aN[r] = ffma2(hv.x, w2.x, aN[r]); aN[r] = ffma2(hv.y, w2.y, aN[r]);
            }
        }
        if (p > 0) {    /* logits for step p-1 from hs_l */
            float part = 0.f;
#pragma unroll 8
            for (int i = 0; i < 64; i++) {
                int iv = (i + lq * 8) & 63;
                int j = lq * 64 + iv;
                part += hs_l[lr * 256 + j] * wos[j * 17 + la];
            }
            part += __shfl_xor_sync(0xffffffffu, part, 1);
            part += __shfl_xor_sync(0xffffffffu, part, 2);
            if (lq == 0) {
                int slot = (row0 + lr) * LMM + (p - 1);
                g_logits[slot * AA + la] = (part + bos[la]) * g_mask[slot];
            }
        }
        __syncthreads();
        /* ---- phase Y: gate math, write hs_l (ys) + hs_w (reset-folded) ---- */
#pragma unroll
        for (int r = 0; r < 4; r++) {
            float2 fR = unpack2(aR[r]), fZ = unpack2(aZ[r]), fN = unpack2(aN[r]);
            float hr = fR.x + fR.y, hz = fZ.x + fZ.y, hn = fN.x + fN.y;
            float rg = 1.f / (1.f + expf(-(gi[r][0] + hr + bh0)));
            float zg = 1.f / (1.f + expf(-(gi[r][1] + hz + bh1)));
            float ng = tanhf(gi[r][2] + rg * (hn + bh2));
            float hnew = (1.f - zg) * ng + zg * h[r];
            hs_l[r * 256 + t] = hnew;
            float heff = hnew;
            if (dfn[r] > 0.5f) heff = g_hid[(size_t)(s0 + r * LMM + 1) * HH + t];
            h[r] = heff;
            hs_w[r * 256 + t] = heff;
        }
        __syncthreads();
    }
    /* epilogue: logits(255) */
    {
        float part = 0.f;
#pragma unroll 8
        for (int i = 0; i < 64; i++) {
            int iv = (i + lq * 8) & 63;
            int j = lq * 64 + iv;
            part += hs_l[lr * 256 + j] * wos[j * 17 + la];
        }
        part += __shfl_xor_sync(0xffffffffu, part, 1);
        part += __shfl_xor_sync(0xffffffffu, part, 2);
        if (lq == 0) {
            int slot = (row0 + lr) * LMM + (LMM - 1);
            g_logits[slot * AA + la] = (part + bos[la]) * g_mask[slot];
        }
    }
}

/* ================= KL + output ================= */
__global__ void kl_k(const float* __restrict__ lm, const float* __restrict__ lv,
                     const float* __restrict__ lmt, const float* __restrict__ lvt) {
    __shared__ float red[256];
    int n = blockIdx.x * 256 + threadIdx.x;
    int t = n >> 5;
    int st = n * LD;
    float s = 0.f;
    const float* ms[2] = {lm, lmt};
    const float* vs[2] = {lv, lvt};
#pragma unroll
    for (int g = 0; g < 2; g++)
        for (int d = 0; d < LD; d++) {
            float mu = ms[g][st + d], logE = vs[g][st + d];
            float m = 0.f, logS = 0.f;
            if (t > 0) { m = ms[g][st - BB * LD + d]; logS = vs[g][st - BB * LD + d]; }
            float dd = m - mu;
            s += logS - logE + expf(logE - logS) + dd * dd * expf(-logS);
        }
    red[threadIdx.x] = 0.5f * (s - 64.f);
    __syncthreads();
    for (int o = 128; o; o >>= 1) {
        if (threadIdx.x < o) red[threadIdx.x] += red[threadIdx.x + o];
        __syncthreads();
    }
    if (threadIdx.x == 0) g_klp[blockIdx.x] = red[0];
}

__global__ void klf_k(float* out) {
    __shared__ float red[512];
    red[threadIdx.x] = g_klp[threadIdx.x];
    __syncthreads();
    for (int o = 256; o; o >>= 1) {
        if (threadIdx.x < o) red[threadIdx.x] += red[threadIdx.x + o];
        __syncthreads();
    }
    if (threadIdx.x == 0) out[0] = red[0];
}

__global__ void out_k(const int* __restrict__ pact, float* __restrict__ dout) {
    int l = blockIdx.x, b = threadIdx.x;
    float acc[16];
#pragma unroll
    for (int a = 0; a < 16; a++) acc[a] = 0.f;
    for (int k = 0; k < KK; k++) {
        int row = b * KK + k;
        int pp = l - (LMM - g_cnt[row]);
        if (pp >= 0) {
            const float* lp = g_logits + (row * LMM + pp) * AA;
#pragma unroll
            for (int a = 0; a < 16; a++) acc[a] += lp[a];
        }
    }
    float mx = acc[0];
#pragma unroll
    for (int a = 1; a < 16; a++) mx = fmaxf(mx, acc[a]);
    float se = 0.f;
#pragma unroll
    for (int a = 0; a < 16; a++) se += expf(acc[a] - mx);
    float lse = logf(se) + mx;
    int act = pact[l * BB + b];
    float lpv = acc[act] - lse;
    for (int o = 16; o; o >>= 1) lpv += __shfl_down_sync(0xffffffffu, lpv, o);
    if (b == 0) dout[1 + l] = lpv;
}

extern "C" void kernel_launch(void* const* d_in, const int* in_sizes, int n_in,
                              void* d_out, int out_size) {
    const float* state = (const float*)d_in[0];
    const float* lmean = (const float*)d_in[1];
    const float* llogv = (const float*)d_in[2];
    const float* lmeant = (const float*)d_in[3];
    const float* llogvt = (const float*)d_in[4];
    const float* achar = (const float*)d_in[5];
    const float* mstate = (const float*)d_in[6];
    const int*   pact   = (const int*)d_in[7];
    const float* dones  = (const float*)d_in[8];
    const float* Wse = (const float*)d_in[9];
    const float* bse = (const float*)d_in[10];
    const float* Wce = (const float*)d_in[11];
    const float* bce = (const float*)d_in[12];
    const float* Wsa = (const float*)d_in[13];
    const float* bsa = (const float*)d_in[14];
    const float* Wh  = (const float*)d_in[15];
    const float* bh  = (const float*)d_in[16];
    const float* Wi  = (const float*)d_in[17];
    const float* bi  = (const float*)d_in[18];
    const float* Whh = (const float*)d_in[19];
    const float* bhh = (const float*)d_in[20];
    const float* Wout = (const float*)d_in[21];
    const float* bout = (const float*)d_in[22];
    float* dout = (float*)d_out;

    static int attr_done = 0;
    size_t rsm = (size_t)16 * G3 * 16 + 4096 + 4096 + 256 * 17 * 4 + 64;  /* 222272 */
    size_t gsm = (size_t)192 * AST * 4 + (size_t)192 * 128 * 4;           /* 150528 */
    if (!attr_done) {
        cudaFuncSetAttribute(recur_k, cudaFuncAttributeMaxDynamicSharedMemorySize, (int)rsm);
        cudaFuncSetAttribute(gemm_k, cudaFuncAttributeMaxDynamicSharedMemorySize, (int)gsm);
        attr_done = 1;
    }

    initprep_k<<<772, 256>>>(dones, Wsa, bsa, Wi, bi, Whh);              /* 0 */
    embed_k<<<NTB / 16, 256>>>(state, achar, mstate, Wse, bse, Wce, bce, Wh, bh); /* 1 */
    gemm_k<<<dim3(NTB / 64, G3 / 128), 256, gsm>>>();                    /* 2 */
    recur_k<<<128, 256, rsm>>>(bhh, Wout, bout);                         /* 3 <- ncu */
    kl_k<<<512, 256>>>(lmean, llogv, lmeant, llogvt);                    /* 4 */
    klf_k<<<1, 512>>>(dout);                                             /* 5 */
    out_k<<<LMM, 32>>>(pact, dout);                                      /* 6 */
}